// round 10
// baseline (speedup 1.0000x reference)
#include <cuda_runtime.h>
#include <cstdint>

#define B_TOT 4096
#define DIN   2048
#define DOUT  2048
// per core: G[r=8][o=512][x=512][s=8], offset = r*2097152 + o*4096 + x*8 + s

__device__ float g_Ghat[4][8][4096];
__device__ float g_S[4][B_TOT][64];
__device__ float g_env[4][B_TOT][64];

// ---------------------------------------------------------------------------
// Kernel 1: Ghat[core][r][p] = sum_o G[core][r][o][p]
// ---------------------------------------------------------------------------
__global__ void k_ghat(const float* __restrict__ c0, const float* __restrict__ c1,
                       const float* __restrict__ c2, const float* __restrict__ c3)
{
    int bid = blockIdx.x, chunk = bid & 15, r = (bid >> 4) & 7, core = bid >> 7;
    const float* G = (core == 0) ? c0 : (core == 1) ? c1 : (core == 2) ? c2 : c3;
    int p = chunk * 256 + threadIdx.x;
    const float* base = G + (size_t)r * 2097152 + p;
    float acc = 0.f;
#pragma unroll 8
    for (int o = 0; o < 512; o++) acc += base[(size_t)o * 4096];
    g_Ghat[core][r][p] = acc;
}

// ---------------------------------------------------------------------------
// Kernel 2: S[core][b][r,s] = sum_x Ghat[core][r][x,s] * X[b][core*512+x]
// ---------------------------------------------------------------------------
__global__ void k_S(const float* __restrict__ X)
{
    __shared__ float xs[4][DIN];
    int t = threadIdx.x, b0 = blockIdx.x * 4;
#pragma unroll
    for (int it = 0; it < 32; it++) {
        int i = t + it * 256;
        xs[i >> 11][i & 2047] = X[(size_t)(b0 + (i >> 11)) * DIN + (i & 2047)];
    }
    __syncthreads();
    int core = t >> 6, rs = t & 63, r = rs >> 3, s = rs & 7;
    const float* gh = g_Ghat[core][r];
    const int xo = core * 512;
    float a0 = 0.f, a1 = 0.f, a2 = 0.f, a3 = 0.f;
#pragma unroll 8
    for (int x = 0; x < 512; x++) {
        float ghv = gh[x * 8 + s];
        a0 += ghv * xs[0][xo + x];
        a1 += ghv * xs[1][xo + x];
        a2 += ghv * xs[2][xo + x];
        a3 += ghv * xs[3][xo + x];
    }
    g_S[core][b0 + 0][rs] = a0;
    g_S[core][b0 + 1][rs] = a1;
    g_S[core][b0 + 2][rs] = a2;
    g_S[core][b0 + 3][rs] = a3;
}

// ---------------------------------------------------------------------------
// Kernel 3: chain products -> env
// ---------------------------------------------------------------------------
__global__ void k_chain()
{
    __shared__ float Sm[4][4][64];
    __shared__ float P2s[4][64], P3s[4][64], Q1s[4][64], Q0s[4][64];
    int t = threadIdx.x, bsub = t >> 6, rs = t & 63, r = rs >> 3, s = rs & 7;
    int b = blockIdx.x * 4 + bsub;
#pragma unroll
    for (int c = 0; c < 4; c++) Sm[bsub][c][rs] = g_S[c][b][rs];
    __syncthreads();
    float p2 = 0.f, q1 = 0.f;
#pragma unroll
    for (int p = 0; p < 8; p++) {
        p2 += Sm[bsub][0][r * 8 + p] * Sm[bsub][1][p * 8 + s];
        q1 += Sm[bsub][2][r * 8 + p] * Sm[bsub][3][p * 8 + s];
    }
    P2s[bsub][rs] = p2; Q1s[bsub][rs] = q1;
    __syncthreads();
    float p3 = 0.f, q0 = 0.f;
#pragma unroll
    for (int p = 0; p < 8; p++) {
        p3 += P2s[bsub][r * 8 + p] * Sm[bsub][2][p * 8 + s];
        q0 += Sm[bsub][1][r * 8 + p] * Q1s[bsub][p * 8 + s];
    }
    P3s[bsub][rs] = p3; Q0s[bsub][rs] = q0;
    __syncthreads();
    float e1 = 0.f, e2 = 0.f;
#pragma unroll
    for (int p = 0; p < 8; p++) {
        e1 += Q1s[bsub][s * 8 + p] * Sm[bsub][0][p * 8 + r];
        e2 += Sm[bsub][3][s * 8 + p] * P2s[bsub][p * 8 + r];
    }
    g_env[0][b][rs] = Q0s[bsub][s * 8 + r];
    g_env[1][b][rs] = e1;
    g_env[2][b][rs] = e2;
    g_env[3][b][rs] = P3s[bsub][s * 8 + r];
}

// ---------------------------------------------------------------------------
// Kernel 4: tf32 mma.sync GEMM, cp.async double-buffered pipeline.
// out[b, core*512+o] = sum_{r,x,s} (env[b,r8+s]*x[b,x]) * G[r,o,x,s]
// CTA 128(M) x 64(N), 8 warps as 4Mx2N, warp tile 32x32.
// 512 stages: r = st>>6, xq = st&63; stage K = 64 floats (8 x * 8 s).
// k-slot permutation: hardware k (tg, tg+4) <-> actual s (2tg, 2tg+1),
// applied consistently to A and B -> B fragment = one LDS.64 of raw fp32,
// converted to tf32 (cvt.rna) at fragment load. Same rounding as before.
// ---------------------------------------------------------------------------
__device__ __forceinline__ uint32_t f2tf32(float f)
{
    uint32_t u;
    asm("cvt.rna.tf32.f32 %0, %1;" : "=r"(u) : "f"(f));
    return u;
}
__device__ __forceinline__ void mma8(float* d, const uint32_t* a, const uint32_t* b)
{
    asm volatile(
        "mma.sync.aligned.m16n8k8.row.col.f32.tf32.tf32.f32 "
        "{%0,%1,%2,%3}, {%4,%5,%6,%7}, {%8,%9}, {%0,%1,%2,%3};\n"
        : "+f"(d[0]), "+f"(d[1]), "+f"(d[2]), "+f"(d[3])
        : "r"(a[0]), "r"(a[1]), "r"(a[2]), "r"(a[3]), "r"(b[0]), "r"(b[1]));
}
__device__ __forceinline__ uint32_t smem_u32(const void* p)
{
    uint32_t a;
    asm("{ .reg .u64 t; cvta.to.shared.u64 t, %1; cvt.u32.u64 %0, t; }" : "=r"(a) : "l"(p));
    return a;
}
#define CP_ASYNC16(dst, src) \
    asm volatile("cp.async.cg.shared.global [%0], [%1], 16;" :: "r"(dst), "l"(src))
#define CP_COMMIT() asm volatile("cp.async.commit_group;" ::: "memory")
#define CP_WAIT0()  asm volatile("cp.async.wait_group 0;" ::: "memory")

#define ENV_LD 66
#define X_LD   12
#define B_LD   72
#define NSTAGE 512
// smem: env[128*66] | x[2][128*12] | B[2][64*72]
#define OFF_X   (128 * ENV_LD)
#define OFF_B   (OFF_X + 2 * 128 * X_LD)
#define SMEM_FLOATS (OFF_B + 2 * 64 * B_LD)
#define SMEM_BYTES  (SMEM_FLOATS * 4)

__global__ void __launch_bounds__(256, 2) k_gemm(
    const float* __restrict__ X,
    const float* __restrict__ c0, const float* __restrict__ c1,
    const float* __restrict__ c2, const float* __restrict__ c3,
    const float* __restrict__ bias, float* __restrict__ out)
{
    extern __shared__ float sm[];
    float* s_env = sm;
    const uint32_t u_x = smem_u32(sm + OFF_X);
    const uint32_t u_B = smem_u32(sm + OFF_B);

    const int core = blockIdx.z;
    const float* G = (core == 0) ? c0 : (core == 1) ? c1 : (core == 2) ? c2 : c3;
    const int m0 = blockIdx.y * 128;
    const int n0 = blockIdx.x * 64;

    const int tid  = threadIdx.x;
    const int lane = tid & 31, warp = tid >> 5;
    const int wm = warp & 3, wn = warp >> 2;
    const int g = lane >> 2, tg = lane & 3;
    const int row0 = wm * 32 + g;

    // per-thread staging coords
    const int bo  = tid >> 4;              // B: o-row 0..63 (wait: tid>>4 in 0..15) -- see below
    // B: 1024 float4 per stage, 4 per thread: idx = tid + i*256 -> o = idx>>4, k16 = idx&15
    const int xrow = tid >> 1;             // x: row 0..127
    const int xj   = (tid & 1) * 4;        // x: float4 within 8
    (void)bo;

    // issue cp.async for stage st into buffer q
    auto stage_async = [&](int st) {
        const int q  = st & 1;
        const int r  = st >> 6, xq = st & 63;
        const float* Gp = G + (size_t)r * 2097152 + (size_t)n0 * 4096 + xq * 64;
#pragma unroll
        for (int i = 0; i < 4; i++) {
            int idx = tid + i * 256;
            int o = idx >> 4, kl = (idx & 15) * 4;
            CP_ASYNC16(u_B + (uint32_t)((q * 64 * B_LD + o * B_LD + kl) * 4),
                       Gp + (size_t)o * 4096 + kl);
        }
        CP_ASYNC16(u_x + (uint32_t)((q * 128 * X_LD + xrow * X_LD + xj) * 4),
                   X + (size_t)(m0 + xrow) * DIN + core * 512 + xq * 8 + xj);
        CP_COMMIT();
    };

    // stage env tile [128][64]
#pragma unroll
    for (int it = 0; it < 32; it++) {
        int i = tid + it * 256;
        int rr = i >> 6, cc = i & 63;
        s_env[rr * ENV_LD + cc] = g_env[core][m0 + rr][cc];
    }
    stage_async(0);

    float acc[2][4][4];
#pragma unroll
    for (int mf = 0; mf < 2; mf++)
#pragma unroll
        for (int nf = 0; nf < 4; nf++)
#pragma unroll
            for (int q = 0; q < 4; q++) acc[mf][nf][q] = 0.f;

    for (int st = 0; st < NSTAGE; st++) {
        const int q = st & 1, r = st >> 6;
        CP_WAIT0();
        __syncthreads();                      // stage st visible; st-1 MMAs done
        if (st + 1 < NSTAGE) stage_async(st + 1);

        const float* s_Bq = sm + OFF_B + q * 64 * B_LD;
        const float* s_xq = sm + OFF_X + q * 128 * X_LD;

        // env pairs for this r: e0[mf]=(env[rw][r8+2tg], env[rw][r8+2tg+1]), e1=rows+8
        float2 e0[2], e1[2];
#pragma unroll
        for (int mf = 0; mf < 2; mf++) {
            int rw = row0 + mf * 16;
            e0[mf] = *(const float2*)(s_env + rw * ENV_LD + r * 8 + 2 * tg);
            e1[mf] = *(const float2*)(s_env + (rw + 8) * ENV_LD + r * 8 + 2 * tg);
        }

#pragma unroll
        for (int xs = 0; xs < 8; xs++) {
            // B fragments: raw fp32 pairs (k-slots tg, tg+4) = s (2tg, 2tg+1)
            uint32_t bf[4][2];
#pragma unroll
            for (int nf = 0; nf < 4; nf++) {
                int o = wn * 32 + nf * 8 + g;
                float2 bp = *(const float2*)(s_Bq + o * B_LD + xs * 8 + tg * 2);
                bf[nf][0] = f2tf32(bp.x);
                bf[nf][1] = f2tf32(bp.y);
            }
            uint32_t af[2][4];
#pragma unroll
            for (int mf = 0; mf < 2; mf++) {
                int rw = row0 + mf * 16;
                float xv0 = s_xq[rw * X_LD + xs];
                float xv1 = s_xq[(rw + 8) * X_LD + xs];
                af[mf][0] = f2tf32(e0[mf].x * xv0);
                af[mf][1] = f2tf32(e1[mf].x * xv1);
                af[mf][2] = f2tf32(e0[mf].y * xv0);
                af[mf][3] = f2tf32(e1[mf].y * xv1);
            }
#pragma unroll
            for (int mf = 0; mf < 2; mf++)
#pragma unroll
                for (int nf = 0; nf < 4; nf++)
                    mma8(acc[mf][nf], af[mf], bf[nf]);
        }
    }

    // Epilogue: c0:(g,2tg) c1:(g,2tg+1) c2:(g+8,2tg) c3:(g+8,2tg+1)
#pragma unroll
    for (int mf = 0; mf < 2; mf++) {
        int row = m0 + row0 + mf * 16;
#pragma unroll
        for (int nf = 0; nf < 4; nf++) {
            int col = core * 512 + n0 + wn * 32 + nf * 8 + 2 * tg;
            out[(size_t)row * DOUT + col]           = acc[mf][nf][0] + bias[col];
            out[(size_t)row * DOUT + col + 1]       = acc[mf][nf][1] + bias[col + 1];
            out[(size_t)(row + 8) * DOUT + col]     = acc[mf][nf][2] + bias[col];
            out[(size_t)(row + 8) * DOUT + col + 1] = acc[mf][nf][3] + bias[col + 1];
        }
    }
}

// ---------------------------------------------------------------------------
extern "C" void kernel_launch(void* const* d_in, const int* in_sizes, int n_in,
                              void* d_out, int out_size)
{
    const float* X    = (const float*)d_in[0];
    const float* c0   = (const float*)d_in[1];
    const float* c1   = (const float*)d_in[2];
    const float* c2   = (const float*)d_in[3];
    const float* c3   = (const float*)d_in[4];
    const float* bias = (const float*)d_in[5];
    float* out = (float*)d_out;

    k_ghat<<<512, 256>>>(c0, c1, c2, c3);
    k_S<<<1024, 256>>>(X);
    k_chain<<<1024, 256>>>();

    cudaFuncSetAttribute(k_gemm, cudaFuncAttributeMaxDynamicSharedMemorySize, SMEM_BYTES);
    dim3 grid(8, 32, 4);   // N-tiles x M-tiles x cores
    k_gemm<<<grid, 256, SMEM_BYTES>>>(X, c0, c1, c2, c3, bias, out);
}

// round 11
// speedup vs baseline: 2.0542x; 2.0542x over previous
#include <cuda_runtime.h>
#include <cuda_fp16.h>
#include <cstdint>

#define B_TOT 4096
#define DIN   2048
#define DOUT  2048
// per core: G[r=8][o=512][x=512][s=8], offset = r*2097152 + o*4096 + x*8 + s

__device__ float g_Ghat[4][8][4096];
__device__ float g_S[4][B_TOT][64];
__device__ float g_env[4][B_TOT][64];
// fp16 copy of G, fragment-interleaved:
// g_Gh[((core*8+r)*512+o)*4096 + xp*16 + p], xp=x/2,
// p = (s>>1)*4 + (x&1)*2 + (s&1)  -> thread tg reads halfs p=4tg..4tg+3
__device__ __half g_Gh[4u * 8u * 512u * 4096u];

// ---------------------------------------------------------------------------
// Kernel 1: Ghat[core][r][p] = sum_o G[core][r][o][p]
// ---------------------------------------------------------------------------
__global__ void k_ghat(const float* __restrict__ c0, const float* __restrict__ c1,
                       const float* __restrict__ c2, const float* __restrict__ c3)
{
    int bid = blockIdx.x, chunk = bid & 15, r = (bid >> 4) & 7, core = bid >> 7;
    const float* G = (core == 0) ? c0 : (core == 1) ? c1 : (core == 2) ? c2 : c3;
    int p = chunk * 256 + threadIdx.x;
    const float* base = G + (size_t)r * 2097152 + p;
    float acc = 0.f;
#pragma unroll 8
    for (int o = 0; o < 512; o++) acc += base[(size_t)o * 4096];
    g_Ghat[core][r][p] = acc;
}

// ---------------------------------------------------------------------------
// Kernel 1b: convert G -> fp16, fragment-interleaved (one 16-float group/thread)
// ---------------------------------------------------------------------------
__global__ void k_gconv(const float* __restrict__ c0, const float* __restrict__ c1,
                        const float* __restrict__ c2, const float* __restrict__ c3)
{
    size_t gid = (size_t)blockIdx.x * 256 + threadIdx.x;   // 4194304 groups
    int core = (int)(gid >> 20);
    size_t woff = gid & 1048575u;
    const float* G = (core == 0) ? c0 : (core == 1) ? c1 : (core == 2) ? c2 : c3;
    const float4* src = (const float4*)(G + woff * 16);
    float f[16];
#pragma unroll
    for (int i = 0; i < 4; i++) {
        float4 v = src[i];
        f[i * 4 + 0] = v.x; f[i * 4 + 1] = v.y; f[i * 4 + 2] = v.z; f[i * 4 + 3] = v.w;
    }
    __half2 h[8];
#pragma unroll
    for (int s2 = 0; s2 < 4; s2++) {
        h[2 * s2]     = __floats2half2_rn(f[2 * s2],     f[2 * s2 + 1]);     // x even
        h[2 * s2 + 1] = __floats2half2_rn(f[8 + 2 * s2], f[8 + 2 * s2 + 1]); // x odd
    }
    uint4* dst = (uint4*)(g_Gh + gid * 16);
    const uint32_t* hu = (const uint32_t*)h;
    dst[0] = make_uint4(hu[0], hu[1], hu[2], hu[3]);
    dst[1] = make_uint4(hu[4], hu[5], hu[6], hu[7]);
}

// ---------------------------------------------------------------------------
// Kernel 2: S[core][b][r,s] = sum_x Ghat[core][r][x,s] * X[b][core*512+x]
// ---------------------------------------------------------------------------
__global__ void k_S(const float* __restrict__ X)
{
    __shared__ float xs[4][DIN];
    int t = threadIdx.x, b0 = blockIdx.x * 4;
#pragma unroll
    for (int it = 0; it < 32; it++) {
        int i = t + it * 256;
        xs[i >> 11][i & 2047] = X[(size_t)(b0 + (i >> 11)) * DIN + (i & 2047)];
    }
    __syncthreads();
    int core = t >> 6, rs = t & 63, r = rs >> 3, s = rs & 7;
    const float* gh = g_Ghat[core][r];
    const int xo = core * 512;
    float a0 = 0.f, a1 = 0.f, a2 = 0.f, a3 = 0.f;
#pragma unroll 8
    for (int x = 0; x < 512; x++) {
        float ghv = gh[x * 8 + s];
        a0 += ghv * xs[0][xo + x];
        a1 += ghv * xs[1][xo + x];
        a2 += ghv * xs[2][xo + x];
        a3 += ghv * xs[3][xo + x];
    }
    g_S[core][b0 + 0][rs] = a0;
    g_S[core][b0 + 1][rs] = a1;
    g_S[core][b0 + 2][rs] = a2;
    g_S[core][b0 + 3][rs] = a3;
}

// ---------------------------------------------------------------------------
// Kernel 3: chain products -> env
// ---------------------------------------------------------------------------
__global__ void k_chain()
{
    __shared__ float Sm[4][4][64];
    __shared__ float P2s[4][64], P3s[4][64], Q1s[4][64], Q0s[4][64];
    int t = threadIdx.x, bsub = t >> 6, rs = t & 63, r = rs >> 3, s = rs & 7;
    int b = blockIdx.x * 4 + bsub;
#pragma unroll
    for (int c = 0; c < 4; c++) Sm[bsub][c][rs] = g_S[c][b][rs];
    __syncthreads();
    float p2 = 0.f, q1 = 0.f;
#pragma unroll
    for (int p = 0; p < 8; p++) {
        p2 += Sm[bsub][0][r * 8 + p] * Sm[bsub][1][p * 8 + s];
        q1 += Sm[bsub][2][r * 8 + p] * Sm[bsub][3][p * 8 + s];
    }
    P2s[bsub][rs] = p2; Q1s[bsub][rs] = q1;
    __syncthreads();
    float p3 = 0.f, q0 = 0.f;
#pragma unroll
    for (int p = 0; p < 8; p++) {
        p3 += P2s[bsub][r * 8 + p] * Sm[bsub][2][p * 8 + s];
        q0 += Sm[bsub][1][r * 8 + p] * Q1s[bsub][p * 8 + s];
    }
    P3s[bsub][rs] = p3; Q0s[bsub][rs] = q0;
    __syncthreads();
    float e1 = 0.f, e2 = 0.f;
#pragma unroll
    for (int p = 0; p < 8; p++) {
        e1 += Q1s[bsub][s * 8 + p] * Sm[bsub][0][p * 8 + r];
        e2 += Sm[bsub][3][s * 8 + p] * P2s[bsub][p * 8 + r];
    }
    g_env[0][b][rs] = Q0s[bsub][s * 8 + r];
    g_env[1][b][rs] = e1;
    g_env[2][b][rs] = e2;
    g_env[3][b][rs] = P3s[bsub][s * 8 + r];
}

// ---------------------------------------------------------------------------
// Kernel 4: f16 mma.m16n8k16 GEMM (fp32 accum), cp.async double-buffered.
// out[b, core*512+o] = sum_{r,x,s} (env[b,r8+s]*x[b,x]) * G[r,o,x,s]
// CTA 128(M) x 64(N), 8 warps 4Mx2N, warp 32x32. 256 stages: r=st>>5,
// xq=st&31; stage K = 16 x * 8 s = 8 k16 blocks. k16 = (x0,x1) x (s0..7):
// thread tg holds k=2tg,2tg+1 (x0) and 2tg+8,2tg+9 (x1) -> B frag is one
// LDS.64 from interleaved g_Gh data; A = env*x in fp32, one rn-round to f16x2.
// ---------------------------------------------------------------------------
__device__ __forceinline__ void mma16(float* d, const uint32_t* a, const uint32_t* b)
{
    asm volatile(
        "mma.sync.aligned.m16n8k16.row.col.f32.f16.f16.f32 "
        "{%0,%1,%2,%3}, {%4,%5,%6,%7}, {%8,%9}, {%0,%1,%2,%3};\n"
        : "+f"(d[0]), "+f"(d[1]), "+f"(d[2]), "+f"(d[3])
        : "r"(a[0]), "r"(a[1]), "r"(a[2]), "r"(a[3]), "r"(b[0]), "r"(b[1]));
}
__device__ __forceinline__ uint32_t smem_u32(const void* p)
{
    uint32_t a;
    asm("{ .reg .u64 t; cvta.to.shared.u64 t, %1; cvt.u32.u64 %0, t; }" : "=r"(a) : "l"(p));
    return a;
}
__device__ __forceinline__ uint32_t pack_h2(float lo, float hi)
{
    __half2 h = __floats2half2_rn(lo, hi);
    return *(uint32_t*)&h;
}
#define CP_ASYNC16(dst, src) \
    asm volatile("cp.async.cg.shared.global [%0], [%1], 16;" :: "r"(dst), "l"(src))
#define CP_COMMIT() asm volatile("cp.async.commit_group;" ::: "memory")
#define CP_WAIT0()  asm volatile("cp.async.wait_group 0;" ::: "memory")

#define NSTAGE   256
#define ENV_LD   66                    // floats per env row
#define XW       20                    // floats per x row (16 data + 4 pad)
#define BROW     288                   // bytes per B o-row (256 data + 32 pad); 72 words == 8 mod 32
#define OFF_ENV  0
#define OFF_X    (128 * ENV_LD * 4)    // 33792
#define XBUF     (128 * XW * 4)        // 10240
#define OFF_B    (OFF_X + 2 * XBUF)    // 54272
#define BBUF     (64 * BROW)           // 18432
#define SMEM_BYTES (OFF_B + 2 * BBUF)  // 91136

__global__ void __launch_bounds__(256, 2) k_gemm(
    const float* __restrict__ X,
    const float* __restrict__ bias, float* __restrict__ out)
{
    extern __shared__ char smc[];
    float* s_env = (float*)(smc + OFF_ENV);
    const uint32_t u_x = smem_u32(smc + OFF_X);
    const uint32_t u_B = smem_u32(smc + OFF_B);

    const int core = blockIdx.z;
    const int m0 = blockIdx.y * 128;
    const int n0 = blockIdx.x * 64;

    const int tid  = threadIdx.x;
    const int lane = tid & 31, warp = tid >> 5;
    const int wm = warp & 3, wn = warp >> 2;
    const int g = lane >> 2, tg = lane & 3;
    const int row0 = wm * 32 + g;

    const __half* GhBase = g_Gh + ((size_t)(core * 8) * 512) * 4096;

    // issue cp.async for stage st into buffer st&1
    auto stage_async = [&](int st) {
        const int q = st & 1, r = st >> 5, xq = st & 31;
        const __half* src = GhBase + ((size_t)r * 512 + n0) * 4096 + xq * 128;
#pragma unroll
        for (int i = 0; i < 4; i++) {
            int idx = tid + i * 256;
            int o = idx >> 4, c = idx & 15;
            CP_ASYNC16(u_B + (uint32_t)(q * BBUF + o * BROW + c * 16),
                       src + (size_t)o * 4096 + c * 8);
        }
        const float* xsrc = X + (size_t)m0 * DIN + core * 512 + xq * 16;
#pragma unroll
        for (int i = 0; i < 2; i++) {
            int idx = tid + i * 256;
            int row = idx >> 2, c = idx & 3;
            CP_ASYNC16(u_x + (uint32_t)(q * XBUF + row * (XW * 4) + c * 16),
                       xsrc + (size_t)row * DIN + c * 4);
        }
        CP_COMMIT();
    };

    // stage env tile [128][64]
#pragma unroll
    for (int it = 0; it < 32; it++) {
        int i = tid + it * 256;
        int rr = i >> 6, cc = i & 63;
        s_env[rr * ENV_LD + cc] = g_env[core][m0 + rr][cc];
    }
    stage_async(0);

    float acc[2][4][4];
#pragma unroll
    for (int mf = 0; mf < 2; mf++)
#pragma unroll
        for (int nf = 0; nf < 4; nf++)
#pragma unroll
            for (int q = 0; q < 4; q++) acc[mf][nf][q] = 0.f;

    float2 e0[2], e1[2];

    for (int st = 0; st < NSTAGE; st++) {
        const int q = st & 1, r = st >> 5;
        CP_WAIT0();
        __syncthreads();                  // stage st visible; prev MMAs done
        if (st + 1 < NSTAGE) stage_async(st + 1);

        if ((st & 31) == 0) {             // env pairs for this r (also covers env tile @st=0)
#pragma unroll
            for (int mf = 0; mf < 2; mf++) {
                int rw = row0 + mf * 16;
                e0[mf] = *(const float2*)(s_env + rw * ENV_LD + r * 8 + 2 * tg);
                e1[mf] = *(const float2*)(s_env + (rw + 8) * ENV_LD + r * 8 + 2 * tg);
            }
        }

        const char*  Bq = smc + OFF_B + q * BBUF;
        const float* xb = (const float*)(smc + OFF_X + q * XBUF);

#pragma unroll
        for (int j = 0; j < 8; j++) {     // 8 k16 blocks (x pair j)
            uint2 bf[4];
#pragma unroll
            for (int nf = 0; nf < 4; nf++) {
                int o = wn * 32 + nf * 8 + g;
                bf[nf] = *(const uint2*)(Bq + o * BROW + j * 32 + tg * 8);
            }
            uint32_t af[2][4];
#pragma unroll
            for (int mf = 0; mf < 2; mf++) {
                int rw = row0 + mf * 16;
                float2 xA = *(const float2*)(xb + rw * XW + 2 * j);
                float2 xB = *(const float2*)(xb + (rw + 8) * XW + 2 * j);
                af[mf][0] = pack_h2(e0[mf].x * xA.x, e0[mf].y * xA.x);
                af[mf][1] = pack_h2(e1[mf].x * xB.x, e1[mf].y * xB.x);
                af[mf][2] = pack_h2(e0[mf].x * xA.y, e0[mf].y * xA.y);
                af[mf][3] = pack_h2(e1[mf].x * xB.y, e1[mf].y * xB.y);
            }
#pragma unroll
            for (int mf = 0; mf < 2; mf++)
#pragma unroll
                for (int nf = 0; nf < 4; nf++)
                    mma16(acc[mf][nf], af[mf], (const uint32_t*)&bf[nf]);
        }
    }

    // Epilogue: c0:(g,2tg) c1:(g,2tg+1) c2:(g+8,2tg) c3:(g+8,2tg+1)
#pragma unroll
    for (int mf = 0; mf < 2; mf++) {
        int row = m0 + row0 + mf * 16;
#pragma unroll
        for (int nf = 0; nf < 4; nf++) {
            int col = core * 512 + n0 + wn * 32 + nf * 8 + 2 * tg;
            out[(size_t)row * DOUT + col]           = acc[mf][nf][0] + bias[col];
            out[(size_t)row * DOUT + col + 1]       = acc[mf][nf][1] + bias[col + 1];
            out[(size_t)(row + 8) * DOUT + col]     = acc[mf][nf][2] + bias[col];
            out[(size_t)(row + 8) * DOUT + col + 1] = acc[mf][nf][3] + bias[col + 1];
        }
    }
}

// ---------------------------------------------------------------------------
extern "C" void kernel_launch(void* const* d_in, const int* in_sizes, int n_in,
                              void* d_out, int out_size)
{
    const float* X    = (const float*)d_in[0];
    const float* c0   = (const float*)d_in[1];
    const float* c1   = (const float*)d_in[2];
    const float* c2   = (const float*)d_in[3];
    const float* c3   = (const float*)d_in[4];
    const float* bias = (const float*)d_in[5];
    float* out = (float*)d_out;

    k_ghat<<<512, 256>>>(c0, c1, c2, c3);
    k_gconv<<<16384, 256>>>(c0, c1, c2, c3);
    k_S<<<1024, 256>>>(X);
    k_chain<<<1024, 256>>>();

    cudaFuncSetAttribute(k_gemm, cudaFuncAttributeMaxDynamicSharedMemorySize, SMEM_BYTES);
    dim3 grid(8, 32, 4);   // N-tiles x M-tiles x cores
    k_gemm<<<grid, 256, SMEM_BYTES>>>(X, bias, out);
}